// round 17
// baseline (speedup 1.0000x reference)
#include <cuda_runtime.h>
#include <math.h>

// Problem constants
#define BB   2
#define TT   2048
#define CC   2048
#define NH_  16
#define HS_  128
#define NLQ_ 512
#define NLKV_ 512
#define DHR_ 64

// ---------------- scratch buffers ----------------
__device__ __align__(16) float d_cq   [(size_t)BB*TT*NLQ_];
__device__ __align__(16) float d_ckv  [(size_t)BB*TT*NLKV_];
__device__ __align__(16) float d_qfull[(size_t)BB*TT*CC];
__device__ __align__(16) float d_vtmp [(size_t)NLKV_*CC];
__device__ __align__(16) float d_qlat [(size_t)BB*NH_*TT*NLKV_];
__device__ __align__(16) float d_qr   [(size_t)BB*TT*NH_*DHR_];
__device__ __align__(16) float d_kr   [(size_t)BB*TT*DHR_];
__device__ __align__(16) float d_ctx  [(size_t)BB*NH_*TT*NLKV_];

// ---------------- tf32 / async helpers ----------------
__device__ __forceinline__ float tf(float x) {
    unsigned r; asm("cvt.rna.tf32.f32 %0, %1;" : "=r"(r) : "f"(x));
    return __uint_as_float(r);
}
__device__ __forceinline__ unsigned tfu(float x) {
    unsigned r; asm("cvt.rna.tf32.f32 %0, %1;" : "=r"(r) : "f"(x));
    return r;
}
__device__ __forceinline__ void mma8(float d[4], const unsigned a[4], const unsigned b[2]) {
    asm volatile(
        "mma.sync.aligned.m16n8k8.row.col.f32.tf32.tf32.f32 "
        "{%0,%1,%2,%3}, {%4,%5,%6,%7}, {%8,%9}, {%0,%1,%2,%3};\n"
        : "+f"(d[0]), "+f"(d[1]), "+f"(d[2]), "+f"(d[3])
        : "r"(a[0]), "r"(a[1]), "r"(a[2]), "r"(a[3]), "r"(b[0]), "r"(b[1]));
}
__device__ __forceinline__ void cp16(unsigned d, const float* s) {
    asm volatile("cp.async.ca.shared.global [%0], [%1], 16;" :: "r"(d), "l"(s));
}
__device__ __forceinline__ void cp_commit() { asm volatile("cp.async.commit_group;"); }
__device__ __forceinline__ void cp_wait2()  { asm volatile("cp.async.wait_group 2;"); }

// ---------------- generic strided fp32 SGEMM (small leftovers only) ----------------
__global__ __launch_bounds__(256) void sgemm_g(
    const float* __restrict__ A, const float* __restrict__ B, float* __restrict__ C,
    int M, int N, int K,
    long long sAm, long long sAk, long long sAb, long long sAh,
    long long sBn, long long sBk, long long sBb, long long sBh,
    long long sCm, long long sCb, long long sCh, int H)
{
    __shared__ float As[16][68];
    __shared__ float Bs[16][68];

    int z = blockIdx.z;
    int bb = z / H, hh = z - bb * H;
    A += (size_t)bb * sAb + (size_t)hh * sAh;
    B += (size_t)bb * sBb + (size_t)hh * sBh;
    C += (size_t)bb * sCb + (size_t)hh * sCh;

    int m0 = blockIdx.y * 64, n0 = blockIdx.x * 64;
    int tid = threadIdx.x;
    int tx = tid & 15, ty = tid >> 4;

    float acc[4][4];
#pragma unroll
    for (int i = 0; i < 4; i++)
#pragma unroll
        for (int j = 0; j < 4; j++) acc[i][j] = 0.f;

    for (int k0 = 0; k0 < K; k0 += 16) {
#pragma unroll
        for (int u = 0; u < 4; u++) {
            int idx = tid * 4 + u;
            int m = idx >> 4, kk = idx & 15;
            int gm = m0 + m, gk = k0 + kk;
            As[kk][m] = (gm < M && gk < K) ? A[(size_t)gm * sAm + (size_t)gk * sAk] : 0.f;
            int gn = n0 + m;
            Bs[kk][m] = (gn < N && gk < K) ? B[(size_t)gn * sBn + (size_t)gk * sBk] : 0.f;
        }
        __syncthreads();
#pragma unroll
        for (int kk = 0; kk < 16; kk++) {
            float4 av = *(const float4*)&As[kk][ty << 2];
            float4 bv = *(const float4*)&Bs[kk][tx << 2];
            float a[4] = {av.x, av.y, av.z, av.w};
            float b[4] = {bv.x, bv.y, bv.z, bv.w};
#pragma unroll
            for (int i = 0; i < 4; i++)
#pragma unroll
                for (int j = 0; j < 4; j++)
                    acc[i][j] = fmaf(a[i], b[j], acc[i][j]);
        }
        __syncthreads();
    }
#pragma unroll
    for (int i = 0; i < 4; i++) {
        int gm = m0 + (ty << 2) + i;
        if (gm >= M) continue;
#pragma unroll
        for (int j = 0; j < 4; j++) {
            int gn = n0 + (tx << 2) + j;
            if (gn < N) C[(size_t)gm * sCm + gn] = acc[i][j];
        }
    }
}

// ---------------- tf32 tensor GEMM, 4-stage cp.async pipeline ----------------
template<int AKC, int BKC>
__global__ __launch_bounds__(256, 2) void tgemm_t(
    const float* __restrict__ A, const float* __restrict__ B, float* __restrict__ C,
    int M, int N, int K,
    long long sAm, long long sAk, long long sAb, long long sAh,
    long long sBn, long long sBk, long long sBb, long long sBh,
    long long sCm, long long sCb, long long sCh, int H)
{
    extern __shared__ float smp[];
    constexpr int ASZ = AKC ? 128 * 20 : 16 * 136;
    constexpr int BSZ = BKC ? 128 * 20 : 16 * 136;
    constexpr int STG = ASZ + BSZ;

    int z = blockIdx.z;
    int bb = z / H, hh = z - bb * H;
    A += (size_t)bb * sAb + (size_t)hh * sAh;
    B += (size_t)bb * sBb + (size_t)hh * sBh;
    C += (size_t)bb * sCb + (size_t)hh * sCh;

    int m0 = blockIdx.y * 128, n0 = blockIdx.x * 128;
    int tid = threadIdx.x, lane = tid & 31, w = tid >> 5;
    int g = lane >> 2, tg = lane & 3;
    int wr = w & 1, wc = w >> 1;

    unsigned sbase = (unsigned)__cvta_generic_to_shared(smp);

    float acc[4][4][4];
#pragma unroll
    for (int i = 0; i < 4; i++)
#pragma unroll
        for (int j = 0; j < 4; j++)
#pragma unroll
            for (int c = 0; c < 4; c++) acc[i][j][c] = 0.f;

    auto issue = [&](int s, int kof) {
        if (AKC) {
            int m = tid >> 1, h2 = (tid & 1) * 8;
            const float* gp = A + (size_t)(m0 + m) * sAm + kof + h2;
            unsigned d = sbase + (unsigned)((s * STG + m * 20 + h2) * 4);
            cp16(d, gp); cp16(d + 16, gp + 4);
        } else {
            int kk = tid & 15, ms = (tid >> 4) * 8;
            const float* gp = A + (size_t)(m0 + ms) + (size_t)(kof + kk) * sAk;
            unsigned d = sbase + (unsigned)((s * STG + kk * 136 + ms) * 4);
            cp16(d, gp); cp16(d + 16, gp + 4);
        }
        if (BKC) {
            int n = tid >> 1, h2 = (tid & 1) * 8;
            const float* gp = B + (size_t)(n0 + n) * sBn + kof + h2;
            unsigned d = sbase + (unsigned)((s * STG + ASZ + n * 20 + h2) * 4);
            cp16(d, gp); cp16(d + 16, gp + 4);
        } else {
            int kk = tid & 15, ns = (tid >> 4) * 8;
            const float* gp = B + (size_t)(n0 + ns) + (size_t)(kof + kk) * sBk;
            unsigned d = sbase + (unsigned)((s * STG + ASZ + kk * 136 + ns) * 4);
            cp16(d, gp); cp16(d + 16, gp + 4);
        }
    };

    const int KT = K >> 4;
    issue(0, 0);  cp_commit();
    issue(1, 16); cp_commit();
    issue(2, 32); cp_commit();
    cp_wait2();
    __syncthreads();

    for (int kt = 0; kt < KT; kt++) {
        int s = kt & 3;
        const float* As_ = smp + s * STG;
        const float* Bs_ = smp + s * STG + ASZ;
#pragma unroll
        for (int kk2 = 0; kk2 < 2; kk2++) {
            int kb = kk2 * 8 + tg;
            unsigned a[4][4], bq[4][2];
#pragma unroll
            for (int ma = 0; ma < 4; ma++) {
                int r = wr * 64 + ma * 16 + g;
                if (AKC) {
                    const float* p = As_ + r * 20 + kb;
                    a[ma][0] = tfu(p[0]);        a[ma][1] = tfu(p[8 * 20]);
                    a[ma][2] = tfu(p[4]);        a[ma][3] = tfu(p[8 * 20 + 4]);
                } else {
                    const float* p = As_ + kb * 136 + r;
                    a[ma][0] = tfu(p[0]);        a[ma][1] = tfu(p[8]);
                    a[ma][2] = tfu(p[4 * 136]);  a[ma][3] = tfu(p[4 * 136 + 8]);
                }
            }
#pragma unroll
            for (int na = 0; na < 4; na++) {
                int c = wc * 32 + na * 8 + g;
                if (BKC) {
                    const float* p = Bs_ + c * 20 + kb;
                    bq[na][0] = tfu(p[0]);       bq[na][1] = tfu(p[4]);
                } else {
                    const float* p = Bs_ + kb * 136 + c;
                    bq[na][0] = tfu(p[0]);       bq[na][1] = tfu(p[4 * 136]);
                }
            }
#pragma unroll
            for (int ma = 0; ma < 4; ma++)
#pragma unroll
                for (int na = 0; na < 4; na++)
                    mma8(acc[ma][na], a[ma], bq[na]);
        }
        if (kt + 3 < KT) issue((kt + 3) & 3, (kt + 3) << 4);
        cp_commit();
        cp_wait2();
        __syncthreads();
    }
#pragma unroll
    for (int ma = 0; ma < 4; ma++)
#pragma unroll
        for (int hf = 0; hf < 2; hf++) {
            int gm = m0 + wr * 64 + ma * 16 + hf * 8 + g;
#pragma unroll
            for (int na = 0; na < 4; na++) {
                int gn = n0 + wc * 32 + na * 8 + 2 * tg;
                float2 o;
                o.x = acc[ma][na][hf * 2];
                o.y = acc[ma][na][hf * 2 + 1];
                *(float2*)&C[(size_t)gm * sCm + gn] = o;
            }
        }
}

// ---------------- RoPE kernels (in-place) ----------------
__global__ void rope_qr_kernel(float* __restrict__ qr,
                               const float* __restrict__ cs, const float* __restrict__ sn)
{
    int idx = blockIdx.x * blockDim.x + threadIdx.x;
    if (idx >= BB * TT * NH_ * 32) return;
    int i  = idx & 31;
    int h  = (idx >> 5) & 15;
    int bt = idx >> 9;
    int t  = bt & (TT - 1);
    float c = cs[t * 32 + i], s = sn[t * 32 + i];
    size_t base = (size_t)bt * (NH_ * DHR_) + h * DHR_ + 2 * i;
    float re = qr[base], im = qr[base + 1];
    qr[base]     = re * c - im * s;
    qr[base + 1] = re * s + im * c;
}

__global__ void rope_kr_kernel(float* __restrict__ kr,
                               const float* __restrict__ cs, const float* __restrict__ sn)
{
    int idx = blockIdx.x * blockDim.x + threadIdx.x;
    if (idx >= BB * TT * 32) return;
    int i  = idx & 31;
    int bt = idx >> 5;
    int t  = bt & (TT - 1);
    float c = cs[t * 32 + i], s = sn[t * 32 + i];
    size_t base = (size_t)bt * DHR_ + 2 * i;
    float re = kr[base], im = kr[base + 1];
    kr[base]     = re * c - im * s;
    kr[base + 1] = re * s + im * c;
}

// ---------------- tf32 flash attention v5: 512 threads, 16 warps ----------------
// 64q x 128k tiles. Warp grid 4(m) x 4(n): S warp tile 16q x 32k, PV 16q x 128v.
// Single smem buffers, register-staged prefetch (fetch next during mma, store after).
#define QCP3 68     // Q chunk pitch (4 mod 32), 64 d per chunk
#define KCP3 136    // K chunk pitch (8 mod 32), 128 keys
#define VPP3 520    // V chunk pitch (8 mod 32), 16 keys per chunk
#define PPX3 132    // P pitch (4 mod 32), 128 keys
#define QSZ3 (64 * QCP3)    // 4352
#define KSZ3 (64 * KCP3)    // 8704
#define VSZ3 (16 * VPP3)    // 8320
#define PSZ3 (64 * PPX3)    // 8448
#define FTC3_FLOATS (QSZ3 + KSZ3 + VSZ3 + PSZ3 + 64*8 + 4*64)   // 30592 fl = 122368 B

__global__ __launch_bounds__(512, 1) void flash_tc3(
    const float* __restrict__ qlat, const float* __restrict__ qr,
    const float* __restrict__ ckv,  const float* __restrict__ kr,
    float* __restrict__ ctx)
{
    extern __shared__ float smx[];
    float* Qs  = smx;                 // [64][QCP3]
    float* Ks  = Qs + QSZ3;           // [64 d][KCP3]  ([d][key])
    float* Vs  = Ks + KSZ3;           // [16][VPP3]    ([key][d])
    float* Ps  = Vs + VSZ3;           // [64][PPX3]
    float* Red = Ps + PSZ3;           // [64][8]
    float* msm = Red + 64 * 8;
    float* lsm = msm + 64;
    float* fsm = lsm + 64;
    float* mns = fsm + 64;

    int qt = blockIdx.x, h = blockIdx.y, b = blockIdx.z;
    int t0 = qt * 64;
    int NT = (qt + 2) >> 1;
    int tid = threadIdx.x, lane = tid & 31, w = tid >> 5;
    int g = lane >> 2, tg = lane & 3;
    int wr = w & 3, wc = w >> 2;
    const float scale = rsqrtf((float)(HS_ + DHR_));

    const float* qlatp = qlat + ((size_t)(b * NH_ + h) * TT + t0) * NLKV_;
    const float* qrp   = qr   + ((size_t)b * TT + t0) * (NH_ * DHR_) + h * DHR_;
    const float* ckvb  = ckv  + (size_t)b * TT * NLKV_;
    const float* krb   = kr   + (size_t)b * TT * DHR_;

    float stg[24];   // unified staging: K in [0..15], Q in [16..23], V in [0..15]

    // Q chunk dc: 64 rows x 64 d -> stg[16..23] (8 fl/thread)
    auto fetchQ = [&](int dc) {
        int r = tid & 63, db = (tid >> 6) * 8;
        const float* src = (dc < 8)
            ? (qlatp + (size_t)r * NLKV_ + dc * 64 + db)
            : (qrp   + (size_t)r * (NH_ * DHR_) + db);
        float4 v0 = *(const float4*)src;
        float4 v1 = *(const float4*)(src + 4);
        stg[16] = v0.x; stg[17] = v0.y; stg[18] = v0.z; stg[19] = v0.w;
        stg[20] = v1.x; stg[21] = v1.y; stg[22] = v1.z; stg[23] = v1.w;
    };
    auto storeQ = [&]() {
        int r = tid & 63, db = (tid >> 6) * 8;
        float* dst = Qs + r * QCP3 + db;
        float4 o0, o1;
        o0.x = tf(stg[16] * scale); o0.y = tf(stg[17] * scale);
        o0.z = tf(stg[18] * scale); o0.w = tf(stg[19] * scale);
        o1.x = tf(stg[20] * scale); o1.y = tf(stg[21] * scale);
        o1.z = tf(stg[22] * scale); o1.w = tf(stg[23] * scale);
        *(float4*)dst = o0; *(float4*)(dst + 4) = o1;
    };
    // K chunk dc: 128 keys x 64 d -> stg[0..15] (16 fl/thread)
    auto fetchK = [&](int s0v, int dc) {
        int j = tid & 127, hf = (tid >> 7) * 16;
        const float* src = (dc < 8)
            ? (ckvb + (size_t)(s0v + j) * NLKV_ + dc * 64 + hf)
            : (krb  + (size_t)(s0v + j) * DHR_ + hf);
#pragma unroll
        for (int u = 0; u < 16; u += 4) {
            float4 v = *(const float4*)(src + u);
            stg[u] = v.x; stg[u+1] = v.y; stg[u+2] = v.z; stg[u+3] = v.w;
        }
    };
    auto storeK = [&]() {
        int j = tid & 127, hf = (tid >> 7) * 16;
#pragma unroll
        for (int u = 0; u < 16; u++) Ks[(hf + u) * KCP3 + j] = tf(stg[u]);
    };
    // V chunk cc: 16 keys x 512 -> stg[0..15]
    auto fetchV = [&](int s0v, int cc) {
#pragma unroll
        for (int u = 0; u < 4; u++) {
            int i4 = tid + u * 512;
            int r = i4 >> 7, c4 = (i4 & 127) * 4;
            float4 v = *(const float4*)(ckvb + (size_t)(s0v + cc * 16 + r) * NLKV_ + c4);
            stg[u*4] = v.x; stg[u*4+1] = v.y; stg[u*4+2] = v.z; stg[u*4+3] = v.w;
        }
    };
    auto storeV = [&]() {
#pragma unroll
        for (int u = 0; u < 4; u++) {
            int i4 = tid + u * 512;
            int r = i4 >> 7, c4 = (i4 & 127) * 4;
            float4 o;
            o.x = tf(stg[u*4]);   o.y = tf(stg[u*4+1]);
            o.z = tf(stg[u*4+2]); o.w = tf(stg[u*4+3]);
            *(float4*)(Vs + r * VPP3 + c4) = o;
        }
    };

    if (tid < 64) { msm[tid] = -1e30f; lsm[tid] = 0.f; }

    float O[16][4];
#pragma unroll
    for (int na = 0; na < 16; na++)
#pragma unroll
        for (int c = 0; c < 4; c++) O[na][c] = 0.f;

    // prime chunk 0 of tile 0
    fetchK(0, 0); fetchQ(0);
    storeK(); storeQ();
    __syncthreads();

    for (int kt2 = 0; kt2 < NT; kt2++) {
        int s0 = kt2 * 128;
        float S[4][4];
#pragma unroll
        for (int na = 0; na < 4; na++)
#pragma unroll
            for (int c = 0; c < 4; c++) S[na][c] = 0.f;

        // ---- S phase: 9 d-chunks, register-staged single-buffer pipeline ----
        for (int dc = 0; dc < 9; dc++) {
            if (dc < 8) { fetchK(s0, dc + 1); fetchQ(dc + 1); }
#pragma unroll
            for (int kk = 0; kk < 8; kk++) {
                unsigned a[4], bq[4][2];
                {
                    const float* p = Qs + (wr * 16 + g) * QCP3 + kk * 8 + tg;
                    a[0] = __float_as_uint(p[0]);
                    a[1] = __float_as_uint(p[8 * QCP3]);
                    a[2] = __float_as_uint(p[4]);
                    a[3] = __float_as_uint(p[8 * QCP3 + 4]);
                }
#pragma unroll
                for (int na = 0; na < 4; na++) {
                    const float* p = Ks + (kk * 8 + tg) * KCP3 + wc * 32 + na * 8 + g;
                    bq[na][0] = __float_as_uint(p[0]);
                    bq[na][1] = __float_as_uint(p[4 * KCP3]);
                }
#pragma unroll
                for (int na = 0; na < 4; na++)
                    mma8(S[na], a, bq[na]);
            }
            __syncthreads();
            if (dc < 8) {
                storeK(); storeQ();
                __syncthreads();
            }
        }

        // causal mask (last tile only; global coords)
        if (kt2 == NT - 1) {
#pragma unroll
            for (int na = 0; na < 4; na++)
#pragma unroll
                for (int ci = 0; ci < 4; ci++) {
                    int row = t0 + wr * 16 + (ci >> 1) * 8 + g;
                    int col = s0 + wc * 32 + na * 8 + 2 * tg + (ci & 1);
                    if (col > row) S[na][ci] = -1e30f;
                }
        }

        // ---- row max ----
#pragma unroll
        for (int hf = 0; hf < 2; hf++) {
            float v = -1e30f;
#pragma unroll
            for (int na = 0; na < 4; na++)
                v = fmaxf(v, fmaxf(S[na][hf * 2], S[na][hf * 2 + 1]));
            v = fmaxf(v, __shfl_xor_sync(0xffffffffu, v, 1));
            v = fmaxf(v, __shfl_xor_sync(0xffffffffu, v, 2));
            if (tg == 0)
                Red[(wr * 16 + hf * 8 + g) * 8 + wc] = v;
        }
        __syncthreads();
        if (tid < 64) {
            float mx = fmaxf(fmaxf(Red[tid * 8 + 0], Red[tid * 8 + 1]),
                             fmaxf(Red[tid * 8 + 2], Red[tid * 8 + 3]));
            float mo = msm[tid];
            float mn = fmaxf(mo, mx);
            msm[tid] = mn; mns[tid] = mn;
            fsm[tid] = __expf(mo - mn);
        }
        __syncthreads();

        // prefetch V chunk 0 (overlaps exp/rescale)
        fetchV(s0, 0);

        // ---- exp, write P (tf32), partial sums, rescale O ----
#pragma unroll
        for (int hf = 0; hf < 2; hf++) {
            int row = wr * 16 + hf * 8 + g;
            float mn = mns[row];
            float s = 0.f;
#pragma unroll
            for (int na = 0; na < 4; na++) {
                float p0 = __expf(S[na][hf * 2 + 0] - mn);
                float p1 = __expf(S[na][hf * 2 + 1] - mn);
                s += p0 + p1;
                float2 pv; pv.x = tf(p0); pv.y = tf(p1);
                *(float2*)(Ps + row * PPX3 + wc * 32 + na * 8 + 2 * tg) = pv;
            }
            s += __shfl_xor_sync(0xffffffffu, s, 1);
            s += __shfl_xor_sync(0xffffffffu, s, 2);
            if (tg == 0) Red[row * 8 + 4 + wc] = s;
        }
        {
            float f0 = fsm[wr * 16 + g];
            float f1 = fsm[wr * 16 + 8 + g];
#pragma unroll
            for (int na = 0; na < 16; na++) {
                O[na][0] *= f0; O[na][1] *= f0;
                O[na][2] *= f1; O[na][3] *= f1;
            }
        }
        __syncthreads();
        if (tid < 64)
            lsm[tid] = lsm[tid] * fsm[tid] +
                       Red[tid * 8 + 4] + Red[tid * 8 + 5] +
                       Red[tid * 8 + 6] + Red[tid * 8 + 7];
        storeV();
        __syncthreads();

        // ---- PV: 8 chunks of 16 keys, register-staged single-buffer pipeline ----
        bool pre = (kt2 < NT - 1);
        for (int cc = 0; cc < 8; cc++) {
            if (cc < 7)       fetchV(s0, cc + 1);
            else if (pre)     { fetchK(s0 + 128, 0); fetchQ(0); }
#pragma unroll
            for (int kk = 0; kk < 2; kk++) {
                unsigned a[4];
                int sc = cc * 16 + kk * 8 + tg;
                {
                    const float* p = Ps + (wr * 16 + g) * PPX3 + sc;
                    a[0] = __float_as_uint(p[0]);
                    a[1] = __float_as_uint(p[8 * PPX3]);
                    a[2] = __float_as_uint(p[4]);
                    a[3] = __float_as_uint(p[8 * PPX3 + 4]);
                }
#pragma unroll
                for (int na = 0; na < 16; na++) {
                    const float* p = Vs + (kk * 8 + tg) * VPP3 + wc * 128 + na * 8 + g;
                    unsigned bq[2];
                    bq[0] = __float_as_uint(p[0]);
                    bq[1] = __float_as_uint(p[4 * VPP3]);
                    mma8(O[na], a, bq);
                }
            }
            __syncthreads();
            if (cc < 7) {
                storeV();
                __syncthreads();
            } else if (pre) {
                storeK(); storeQ();
                __syncthreads();
            }
        }
    }

    // ---- epilogue: normalize and write ctx ----
#pragma unroll
    for (int hf = 0; hf < 2; hf++) {
        int row = wr * 16 + hf * 8 + g;
        float inv = 1.0f / lsm[row];
        float* orow = ctx + ((size_t)(b * NH_ + h) * TT + t0 + row) * NLKV_;
#pragma unroll
        for (int na = 0; na < 16; na++) {
            float2 o;
            o.x = O[na][hf * 2]     * inv;
            o.y = O[na][hf * 2 + 1] * inv;
            *(float2*)(orow + wc * 128 + na * 8 + 2 * tg) = o;
        }
    }
}

// ---------------- launch ----------------
extern "C" void kernel_launch(void* const* d_in, const int* in_sizes, int n_in,
                              void* d_out, int out_size)
{
    (void)in_sizes; (void)n_in; (void)out_size;
    const float* x    = (const float*)d_in[0];
    const float* cs   = (const float*)d_in[1];
    const float* sn   = (const float*)d_in[2];
    const float* W_dq = (const float*)d_in[3];
    const float* W_uq = (const float*)d_in[4];
    const float* W_dkv= (const float*)d_in[5];
    const float* W_uk = (const float*)d_in[6];
    const float* W_uv = (const float*)d_in[7];
    const float* W_qr = (const float*)d_in[8];
    const float* W_kr = (const float*)d_in[9];
    const float* W_o  = (const float*)d_in[10];
    float* y = (float*)d_out;

    float *cq, *ckv, *qfull, *vtmp, *qlat, *qr, *kr, *ctx;
    cudaGetSymbolAddress((void**)&cq,    d_cq);
    cudaGetSymbolAddress((void**)&ckv,   d_ckv);
    cudaGetSymbolAddress((void**)&qfull, d_qfull);
    cudaGetSymbolAddress((void**)&vtmp,  d_vtmp);
    cudaGetSymbolAddress((void**)&qlat,  d_qlat);
    cudaGetSymbolAddress((void**)&qr,    d_qr);
    cudaGetSymbolAddress((void**)&kr,    d_kr);
    cudaGetSymbolAddress((void**)&ctx,   d_ctx);

    const int MT = BB * TT;   // 4096

    const int smem11 = 4 * (128*20 + 128*20) * 4;
    const int smem10 = 4 * (128*20 + 16*136) * 4;
    const int smem01 = 4 * (16*136 + 128*20) * 4;
    cudaFuncSetAttribute((const void*)tgemm_t<1,1>,
                         cudaFuncAttributeMaxDynamicSharedMemorySize, smem11);
    cudaFuncSetAttribute((const void*)tgemm_t<1,0>,
                         cudaFuncAttributeMaxDynamicSharedMemorySize, smem10);
    cudaFuncSetAttribute((const void*)tgemm_t<0,1>,
                         cudaFuncAttributeMaxDynamicSharedMemorySize, smem01);

    // 1) c_q = x @ W_dq^T
    tgemm_t<1,1><<<dim3(NLQ_/128, MT/128, 1), 256, smem11>>>(x, W_dq, cq,
        MT, NLQ_, CC,  CC,1, 0,0,  CC,1, 0,0,  NLQ_, 0,0, 1);

    // 2) c_kv = x @ W_dkv^T
    tgemm_t<1,1><<<dim3(NLKV_/128, MT/128, 1), 256, smem11>>>(x, W_dkv, ckv,
        MT, NLKV_, CC,  CC,1, 0,0,  CC,1, 0,0,  NLKV_, 0,0, 1);

    // 3) q_full = c_q @ W_uq   (rank-128 factorization, stage 1)
    tgemm_t<1,0><<<dim3(CC/128, MT/128, 1), 256, smem10>>>(cq, W_uq, qfull,
        MT, CC, NLQ_,
        NLQ_,1, 0,0,
        1,(long long)CC, 0,0,
        CC, 0,0, 1);

    // 4) v_tmp = W_uv^T @ W_o^T
    tgemm_t<0,1><<<dim3(CC/128, NLKV_/128, 1), 256, smem01>>>(W_uv, W_o, vtmp,
        NLKV_, CC, CC,
        1,(long long)NLKV_, 0,0,
        CC,1, 0,0,
        CC, 0,0, 1);

    // 5) qr_lin = c_q @ W_qr^T
    tgemm_t<1,1><<<dim3((NH_*DHR_)/128, MT/128, 1), 256, smem11>>>(cq, W_qr, qr,
        MT, NH_*DHR_, NLQ_,  NLQ_,1, 0,0,  NLQ_,1, 0,0,  NH_*DHR_, 0,0, 1);

    // 6) kr_lin = x @ W_kr^T   (fp32, small)
    sgemm_g<<<dim3(1, MT/64, 1), 256>>>(x, W_kr, kr,
        MT, DHR_, CC,  CC,1, 0,0,  CC,1, 0,0,  DHR_, 0,0, 1);

    // 7) RoPE (in place)
    rope_qr_kernel<<<(BB*TT*NH_*32 + 255)/256, 256>>>(qr, cs, sn);
    rope_kr_kernel<<<(BB*TT*32 + 255)/256, 256>>>(kr, cs, sn);

    // 8) q_lat[b,h] = q_full_h @ W_uk_h   (K=128)
    tgemm_t<1,0><<<dim3(NLKV_/128, TT/128, BB*NH_), 256, smem10>>>(qfull, W_uk, qlat,
        TT, NLKV_, HS_,
        CC,1, (long long)TT*CC, (long long)HS_,
        1,(long long)NLKV_, 0,(long long)HS_*NLKV_,
        NLKV_, (long long)NH_*TT*NLKV_, (long long)TT*NLKV_, NH_);

    // 9) flash attention v5 (512 threads, 16 warps) -> ctx
    static const size_t smem_bytes = (size_t)FTC3_FLOATS * sizeof(float);
    cudaFuncSetAttribute(flash_tc3, cudaFuncAttributeMaxDynamicSharedMemorySize,
                         (int)smem_bytes);
    flash_tc3<<<dim3(TT/64, NH_, BB), 512, smem_bytes>>>(qlat, qr, ckv, kr, ctx);

    // 10) y = ctx @ v_eff
    tgemm_t<1,0><<<dim3(HS_/128, TT/128, BB*NH_), 256, smem10>>>(ctx, vtmp, y,
        TT, HS_, NLKV_,
        NLKV_,1, (long long)NH_*TT*NLKV_, (long long)TT*NLKV_,
        1,(long long)CC, 0,(long long)HS_,
        CC, (long long)TT*CC, (long long)HS_, NH_);
}